// round 16
// baseline (speedup 1.0000x reference)
#include <cuda_runtime.h>
#include <cuda_fp16.h>
#include <math.h>
#include <stdint.h>
#include <mma.h>

using namespace nvcuda;

// ---------------- problem constants ----------------
#define BATCH   2
#define SEQLEN  2048
#define DMODEL  1024
#define DINNER  2048
#define DSTATE  16
#define DTRANK  64
#define NTOK    (BATCH * SEQLEN)           // 4096
#define XPW     96                         // logical width of xproj output
#define XPP     128                        // padded width (fp16 TC friendly)

// ---------------- scratch (device globals; no cudaMalloc allowed) ----------------
__device__ __half g_xzh[NTOK * 2 * DINNER];      // (4096, 4096) fp16: xi | z
__device__ __half g_xsh[NTOK * DINNER];          // conv+silu output (fp16)
__device__ float  g_xp[NTOK * XPP];              // dt | B | C (padded to 128)
__device__ __half g_xph[NTOK * DTRANK];          // dt columns in fp16 (G3 A)
__device__ float  g_delta[NTOK * DINNER];        // softplus(dt @ W_dt + b_dt)
__device__ float  g_part[8 * NTOK * XPP];        // split-K partials for G2
__device__ __half g_xh[NTOK * DMODEL];           // x in fp16
__device__ __half g_winh[DMODEL * 2 * DINNER];   // W_in in fp16
__device__ __half g_wouth[DINNER * DMODEL];      // W_out in fp16
__device__ __half g_wxh[DINNER * XPP];           // W_xproj fp16, zero-padded
__device__ __half g_wdth[DTRANK * DINNER];       // W_dt in fp16
__device__ __half g_yh[NTOK * DINNER];           // gated scan output in fp16

// ---------------- cp.async helpers ----------------
__device__ __forceinline__ void cp_async16(void* smem_dst, const void* gmem_src) {
    unsigned saddr = (unsigned)__cvta_generic_to_shared(smem_dst);
    asm volatile("cp.async.cg.shared.global [%0], [%1], 16;\n" :: "r"(saddr), "l"(gmem_src));
}
__device__ __forceinline__ void cp_async_commit() {
    asm volatile("cp.async.commit_group;\n" ::);
}
template <int N>
__device__ __forceinline__ void cp_async_wait() {
    asm volatile("cp.async.wait_group %0;\n" :: "n"(N));
}

// ---------------- prepass: only x + W_in (needed before G1) --------------------
#define PRE_N0 (NTOK * DMODEL / 4)            // x     (float4 units)
#define PRE_N1 (DMODEL * 2 * DINNER / 4)      // W_in
#define PRE_TOTAL (PRE_N0 + PRE_N1)

__global__ void prepass_kernel(const float4* __restrict__ x,
                               const float4* __restrict__ W_in,
                               __half2* __restrict__ xh,
                               __half2* __restrict__ winh)
{
    int i = blockIdx.x * blockDim.x + threadIdx.x;
    if (i >= PRE_TOTAL) return;
    const float4* src;
    __half2* dst;
    if (i < PRE_N0) { src = x; dst = xh; }
    else { i -= PRE_N0; src = W_in; dst = winh; }
    float4 v = src[i];
    dst[2 * i + 0] = __floats2half2_rn(v.x, v.y);
    dst[2 * i + 1] = __floats2half2_rn(v.z, v.w);
}

// ---------------- FP16 tensor-core GEMM (frozen R10 mainloop) ------------------
// EPI=0: fp32 C store.  EPI=1: softplus(acc+bias) fp32.  EPI=2: fp16 C store.
#define LDA_H  24
#define LDB_H  136

template <int EPI>
__global__ void __launch_bounds__(128, 2)
gemm_h(const __half* __restrict__ A, int lda,
       const __half* __restrict__ B, int ldb,
       float* __restrict__ C, int ldc, int Kslice,
       const float* __restrict__ bias, long long c_slice_stride)
{
    __shared__ __half sA[3][128][LDA_H];
    __shared__ __half sB[3][16][LDB_H];

    const int bm  = blockIdx.y * 128;
    const int bn  = blockIdx.x * 128;
    const int tid = threadIdx.x;
    const int warp = tid >> 5;
    const int wr = warp >> 1;
    const int wc = warp & 1;

    A += blockIdx.z * Kslice;
    B += (size_t)blockIdx.z * Kslice * ldb;
    C += (long long)blockIdx.z * c_slice_stride;

    wmma::fragment<wmma::accumulator, 16, 16, 16, float> acc[4][4];
#pragma unroll
    for (int i = 0; i < 4; i++)
#pragma unroll
        for (int j = 0; j < 4; j++) wmma::fill_fragment(acc[i][j], 0.f);

    const int a_r0 = tid >> 1;
    const int a_h  = (tid & 1) * 8;
    const int b_r0 = tid >> 4;
    const int b_h  = (tid & 15) * 8;

    const int T = Kslice >> 4;

    auto load_stage = [&](int s, int t) {
        const __half* gA = A + (size_t)bm * lda + t * 16;
        cp_async16(&sA[s][a_r0][a_h],      gA + (size_t)a_r0 * lda + a_h);
        cp_async16(&sA[s][a_r0 + 64][a_h], gA + (size_t)(a_r0 + 64) * lda + a_h);
        const __half* gB = B + (size_t)(t * 16) * ldb + bn;
        cp_async16(&sB[s][b_r0][b_h],     gB + (size_t)b_r0 * ldb + b_h);
        cp_async16(&sB[s][b_r0 + 8][b_h], gB + (size_t)(b_r0 + 8) * ldb + b_h);
        cp_async_commit();
    };

    load_stage(0, 0);
    if (T > 1) load_stage(1, 1); else cp_async_commit();

    for (int t = 0; t < T; t++) {
        cp_async_wait<1>();
        __syncthreads();

        if (t + 2 < T) load_stage((t + 2) % 3, t + 2);
        else           cp_async_commit();

        const int s = t % 3;
        wmma::fragment<wmma::matrix_a, 16, 16, 16, __half, wmma::row_major> af[4];
        wmma::fragment<wmma::matrix_b, 16, 16, 16, __half, wmma::row_major> bf[4];
#pragma unroll
        for (int i = 0; i < 4; i++)
            wmma::load_matrix_sync(af[i], &sA[s][wr * 64 + i * 16][0], LDA_H);
#pragma unroll
        for (int j = 0; j < 4; j++)
            wmma::load_matrix_sync(bf[j], &sB[s][0][wc * 64 + j * 16], LDB_H);
#pragma unroll
        for (int i = 0; i < 4; i++)
#pragma unroll
            for (int j = 0; j < 4; j++)
                wmma::mma_sync(acc[i][j], af[i], bf[j], acc[i][j]);
    }

    if (EPI == 0) {
#pragma unroll
        for (int i = 0; i < 4; i++)
#pragma unroll
            for (int j = 0; j < 4; j++) {
                float* dst = C + (size_t)(bm + wr * 64 + i * 16) * ldc
                               + bn + wc * 64 + j * 16;
                wmma::store_matrix_sync(dst, acc[i][j], ldc, wmma::mem_row_major);
            }
    } else if (EPI == 1) {
        __syncthreads();
        float* stage = reinterpret_cast<float*>(&sA[0][0][0]) + warp * 256;
        const int lane = tid & 31;
#pragma unroll
        for (int i = 0; i < 4; i++)
#pragma unroll
            for (int j = 0; j < 4; j++) {
                wmma::store_matrix_sync(stage, acc[i][j], 16, wmma::mem_row_major);
                __syncwarp();
#pragma unroll
                for (int e = 0; e < 8; e++) {
                    const int idx = lane * 8 + e;
                    const int r = idx >> 4, c = idx & 15;
                    const int gcol = bn + wc * 64 + j * 16 + c;
                    float v = stage[idx] + bias[gcol];
                    v = (v > 20.f) ? v : log1pf(expf(v));
                    C[(size_t)(bm + wr * 64 + i * 16 + r) * ldc + gcol] = v;
                }
                __syncwarp();
            }
    } else {
        // EPI==2: fp16 store via per-warp smem staging, __half2 writes
        __syncthreads();
        float* stage = reinterpret_cast<float*>(&sA[0][0][0]) + warp * 256;
        __half* C16 = reinterpret_cast<__half*>(C);
        const int lane = tid & 31;
#pragma unroll
        for (int i = 0; i < 4; i++)
#pragma unroll
            for (int j = 0; j < 4; j++) {
                wmma::store_matrix_sync(stage, acc[i][j], 16, wmma::mem_row_major);
                __syncwarp();
#pragma unroll
                for (int e = 0; e < 8; e += 2) {
                    const int idx = lane * 8 + e;
                    const int r = idx >> 4, c = idx & 15;
                    const int grow = bm + wr * 64 + i * 16 + r;
                    const int gcol = bn + wc * 64 + j * 16 + c;
                    __half2 hv = __floats2half2_rn(stage[idx], stage[idx + 1]);
                    *reinterpret_cast<__half2*>(C16 + (size_t)grow * ldc + gcol) = hv;
                }
                __syncwarp();
            }
    }
}

// ---------------- conv (fp16 in/out) + fused late weight conversions -----------
#define CONV_T   ((NTOK / 4) * DINNER)        // 2,097,152 conv work items
#define CV_N2    (DINNER * DMODEL / 4)        // W_out float4 units
#define CV_N3    (DTRANK * DINNER / 4)        // W_dt float4 units
#define CV_N4    (DINNER * XPP)               // W_xproj pad half units
#define CONV_TOTAL (CONV_T + CV_N2 + CV_N3 + CV_N4)

__global__ void conv_silu_kernel(const __half* __restrict__ xzh,
                                 const float* __restrict__ cw,
                                 const float* __restrict__ cb,
                                 __half* __restrict__ xsh,
                                 const float4* __restrict__ W_out,
                                 const float4* __restrict__ W_dt,
                                 const float*  __restrict__ W_xproj,
                                 __half2* __restrict__ wouth,
                                 __half2* __restrict__ wdth,
                                 __half*  __restrict__ wxh)
{
    int gidx = blockIdx.x * blockDim.x + threadIdx.x;
    if (gidx < CONV_T) {
        const int d  = gidx & (DINNER - 1);
        const int tq = gidx >> 11;
        const int tok0 = tq * 4;
        const bool first = ((tok0 & (SEQLEN - 1)) == 0);

        const float w0 = cw[d * 4 + 0];
        const float w1 = cw[d * 4 + 1];
        const float w2 = cw[d * 4 + 2];
        const float w3 = cw[d * 4 + 3];
        const float bb = cb[d];

        float a[7];
        const __half* base = xzh + (size_t)tok0 * (2 * DINNER) + d;
        if (first) { a[0] = a[1] = a[2] = 0.f; }
        else {
            a[0] = __half2float(base[-3 * (2 * DINNER)]);
            a[1] = __half2float(base[-2 * (2 * DINNER)]);
            a[2] = __half2float(base[-1 * (2 * DINNER)]);
        }
#pragma unroll
        for (int i = 0; i < 4; i++)
            a[3 + i] = __half2float(base[i * (2 * DINNER)]);

#pragma unroll
        for (int i = 0; i < 4; i++) {
            const float acc = bb + w0 * a[i] + w1 * a[i + 1] + w2 * a[i + 2] + w3 * a[i + 3];
            const float v = acc / (1.f + __expf(-acc));
            xsh[(size_t)(tok0 + i) * DINNER + d] = __float2half_rn(v);
        }
        return;
    }
    // late weight conversions (ride in conv's shadow; needed from G2 onward)
    int i = gidx - CONV_T;
    if (i < CV_N2) {
        float4 v = W_out[i];
        wouth[2 * i + 0] = __floats2half2_rn(v.x, v.y);
        wouth[2 * i + 1] = __floats2half2_rn(v.z, v.w);
        return;
    }
    i -= CV_N2;
    if (i < CV_N3) {
        float4 v = W_dt[i];
        wdth[2 * i + 0] = __floats2half2_rn(v.x, v.y);
        wdth[2 * i + 1] = __floats2half2_rn(v.z, v.w);
        return;
    }
    i -= CV_N3;
    if (i < CV_N4) {
        const int r = i >> 7, c = i & 127;
        wxh[i] = (c < XPW) ? __float2half_rn(W_xproj[r * XPW + c])
                           : __float2half_rn(0.f);
    }
}

// ---------------- split-K reduction: part[8] -> xp fp32 + xph fp16 ------------
__global__ void reduce8_kernel(const float* __restrict__ part,
                               float* __restrict__ xp,
                               __half* __restrict__ xph)
{
    const int i = blockIdx.x * blockDim.x + threadIdx.x;
    if (i >= NTOK * XPP) return;
    float s = 0.f;
#pragma unroll
    for (int k = 0; k < 8; k++) s += part[(size_t)k * (NTOK * XPP) + i];
    xp[i] = s;
    const int col = i & 127;
    if (col < DTRANK) xph[(size_t)(i >> 7) * DTRANK + col] = __float2half_rn(s);
}

// ---------------- selective scan + skip + gate: 16 channels/block -------------
#define STT 32
#define HCP 17
// smem: sB/sC/sd fp32 (2x32x16 each), szh/sxh fp16 (2x32x16), sHC, sDp
#define SCAN_SMEM (3 * (2 * STT * 16) * 4 + 2 * (2 * STT * 16) * 2 + (STT * 16 * HCP) * 4 + 64)

__global__ void __launch_bounds__(256)
scan_kernel(const float* __restrict__ delta,
            const __half* __restrict__ xsh,
            const float* __restrict__ xp,
            const __half* __restrict__ xzh,
            const float* __restrict__ A_log,
            const float* __restrict__ Dpar,
            __half* __restrict__ y)
{
    extern __shared__ float smem[];
    float*  sB  = smem;                        // 1024 f
    float*  sC  = sB + 2 * STT * 16;           // 1024 f
    float*  sd  = sC + 2 * STT * 16;           // 1024 f
    __half* szh = (__half*)(sd + 2 * STT * 16);            // 1024 h
    __half* sxh = szh + 2 * STT * 16;                      // 1024 h
    float*  sHC = (float*)(sxh + 2 * STT * 16);            // STT*16*HCP f
    float*  sDp = sHC + STT * 16 * HCP;                    // 16 f

    const int b    = blockIdx.y;
    const int d0   = blockIdx.x * 16;
    const int tid  = threadIdx.x;
    const int lane = tid & 31;
    const int warp = tid >> 5;
    const int grp  = lane >> 4;
    const int n    = lane & 15;
    const int ch   = warp * 2 + grp;
    const int d    = d0 + ch;

    const float An = -__expf(A_log[d * DSTATE + n]);
    if (tid < 16) sDp[tid] = Dpar[d0 + tid];
    float h = 0.f;

    const int T = SEQLEN / STT;

    auto stage = [&](int buf, int l0) {
        // B/C: 8 fp32 chunks per token, 256 total -> 1 per thread
        {
            const int t = tid >> 3, j = tid & 7;
            const float* row = xp + (size_t)(b * SEQLEN + l0 + t) * XPP + DTRANK;
            if (j < 4) cp_async16(&sB[buf * 512 + t * 16 + j * 4], row + j * 4);
            else       cp_async16(&sC[buf * 512 + t * 16 + (j - 4) * 4],
                                  row + DSTATE + (j - 4) * 4);
        }
        // delta: 4 fp32 chunks per token (128 items)
        if (tid < STT * 4) {
            const int t = tid >> 2, c4 = (tid & 3) * 4;
            const size_t tok = (size_t)(b * SEQLEN + l0 + t);
            cp_async16(&sd[buf * 512 + t * 16 + c4], delta + tok * DINNER + d0 + c4);
        }
        // x, z (fp16): 2 chunks per token each (64 items each)
        if (tid < STT * 2) {
            const int t = tid >> 1, c8 = (tid & 1) * 8;
            const size_t tok = (size_t)(b * SEQLEN + l0 + t);
            cp_async16(&sxh[buf * 512 + t * 16 + c8], xsh + tok * DINNER + d0 + c8);
            cp_async16(&szh[buf * 512 + t * 16 + c8],
                       xzh + tok * (2 * DINNER) + DINNER + d0 + c8);
        }
    };

    stage(0, 0);
    cp_async_commit();

    for (int ti = 0; ti < T; ti++) {
        if (ti + 1 < T) stage((ti + 1) & 1, (ti + 1) * STT);
        cp_async_commit();

        cp_async_wait<1>();
        __syncthreads();

        const int buf = ti & 1;
        const int l0  = ti * STT;

#pragma unroll 8
        for (int t = 0; t < STT; t++) {
            const float dt = sd[buf * 512 + t * 16 + ch];
            const float xt = __half2float(sxh[buf * 512 + t * 16 + ch]);
            const float dA = __expf(dt * An);
            h = fmaf(dA, h, dt * xt * sB[buf * 512 + t * 16 + n]);
            sHC[t * (16 * HCP) + ch * HCP + n] = h * sC[buf * 512 + t * 16 + n];
        }
        __syncthreads();

#pragma unroll
        for (int o = tid; o < STT * 16; o += 256) {
            const int t = o >> 4, c = o & 15;
            const float* p = &sHC[t * (16 * HCP) + c * HCP];
            float s = 0.f;
#pragma unroll
            for (int j = 0; j < 16; j++) s += p[j];
            const float zz = __half2float(szh[buf * 512 + t * 16 + c]);
            const float zs = zz / (1.f + __expf(-zz));
            const float xt = __half2float(sxh[buf * 512 + t * 16 + c]);
            const float val = (s + sDp[c] * xt) * zs;
            y[(size_t)(b * SEQLEN + l0 + t) * DINNER + d0 + c] = __float2half_rn(val);
        }
        __syncthreads();
    }
}

// ---------------- launcher ----------------
extern "C" void kernel_launch(void* const* d_in, const int* in_sizes, int n_in,
                              void* d_out, int out_size)
{
    const float* x       = (const float*)d_in[0];
    const float* W_in    = (const float*)d_in[1];
    const float* conv_w  = (const float*)d_in[2];
    const float* conv_b  = (const float*)d_in[3];
    const float* W_xproj = (const float*)d_in[4];
    const float* W_dt    = (const float*)d_in[5];
    const float* b_dt    = (const float*)d_in[6];
    const float* A_log   = (const float*)d_in[7];
    const float* Dpar    = (const float*)d_in[8];
    const float* W_out   = (const float*)d_in[9];
    float* out = (float*)d_out;

    float *xp, *delta, *part;
    __half *xzh, *xh, *winh, *wouth, *yh, *xsh, *xph, *wxh, *wdth;
    cudaGetSymbolAddress((void**)&xzh,   g_xzh);
    cudaGetSymbolAddress((void**)&xsh,   g_xsh);
    cudaGetSymbolAddress((void**)&xp,    g_xp);
    cudaGetSymbolAddress((void**)&xph,   g_xph);
    cudaGetSymbolAddress((void**)&delta, g_delta);
    cudaGetSymbolAddress((void**)&part,  g_part);
    cudaGetSymbolAddress((void**)&xh,    g_xh);
    cudaGetSymbolAddress((void**)&winh,  g_winh);
    cudaGetSymbolAddress((void**)&wouth, g_wouth);
    cudaGetSymbolAddress((void**)&wxh,   g_wxh);
    cudaGetSymbolAddress((void**)&wdth,  g_wdth);
    cudaGetSymbolAddress((void**)&yh,    g_yh);

    cudaFuncSetAttribute(scan_kernel, cudaFuncAttributeMaxDynamicSharedMemorySize,
                         SCAN_SMEM);

    // prepass: x + W_in only (G1's inputs)
    prepass_kernel<<<(PRE_TOTAL + 255) / 256, 256>>>(
        (const float4*)x, (const float4*)W_in, (__half2*)xh, (__half2*)winh);

    // G1: xzh = x @ W_in  (fp16 output)
    gemm_h<2><<<dim3((2 * DINNER) / 128, NTOK / 128, 1), 128>>>(
        xh, DMODEL, winh, 2 * DINNER, (float*)xzh, 2 * DINNER, DMODEL, nullptr, 0);

    // conv + SiLU -> xsh; late weight conversions fused into same launch
    conv_silu_kernel<<<(CONV_TOTAL + 255) / 256, 256>>>(
        xzh, conv_w, conv_b, xsh,
        (const float4*)W_out, (const float4*)W_dt, W_xproj,
        (__half2*)wouth, (__half2*)wdth, wxh);

    // G2 (fp16 TC, split-K=8): part = xs @ W_xproj_pad
    gemm_h<0><<<dim3(1, NTOK / 128, 8), 128>>>(
        xsh, DINNER, wxh, XPP, part, XPP, DINNER / 8, nullptr,
        (long long)NTOK * XPP);
    reduce8_kernel<<<(NTOK * XPP + 255) / 256, 256>>>(part, xp, xph);

    // G3 (fp16 TC): delta = softplus(xph @ W_dt + b_dt)
    gemm_h<1><<<dim3(DINNER / 128, NTOK / 128, 1), 128>>>(
        xph, DTRANK, wdth, DINNER, delta, DINNER, DTRANK, b_dt, 0);

    // selective scan + D*x skip + silu(z) gate -> yh (fp16)
    scan_kernel<<<dim3(DINNER / 16, BATCH), 256, SCAN_SMEM>>>(
        delta, xsh, xp, xzh, A_log, Dpar, yh);

    // G4: out = y @ W_out  (fp32 output)
    gemm_h<0><<<dim3(DMODEL / 128, NTOK / 128, 1), 128>>>(
        yh, DINNER, wouth, DMODEL, out, DMODEL, DINNER, nullptr, 0);
}